// round 1
// baseline (speedup 1.0000x reference)
#include <cuda_runtime.h>

#define N_NODES 100000
#define N_EDGES 1600000
#define DIN 48
#define DU 128
#define DOUT 128
#define OUT_ELEMS (N_NODES * DOUT)           // 12,800,000
#define FULL_OUT  (OUT_ELEMS + 3 * N_EDGES + N_NODES)  // 17,700,000

// Scratch node-feature buffers (19.2 MB each) — L2-resident working set.
__device__ float g_bufA[(size_t)N_NODES * DIN];
__device__ float g_bufB[(size_t)N_NODES * DIN];

// ---------------------------------------------------------------------------
// Zero both scratch buffers (float4 vectorized).
// ---------------------------------------------------------------------------
__global__ void zero_bufs()
{
    int i = blockIdx.x * blockDim.x + threadIdx.x;
    if (i < N_NODES * DIN / 4) {
        ((float4*)g_bufA)[i] = make_float4(0.f, 0.f, 0.f, 0.f);
        ((float4*)g_bufB)[i] = make_float4(0.f, 0.f, 0.f, 0.f);
    }
}

// ---------------------------------------------------------------------------
// One message-passing scatter: dst[end[e]] += src[start[e]] * dfs[e]
// 12 float4 chunks per edge (48 floats). Consecutive threads share an edge,
// so gathers and atomics are coalesced within the 192B row.
// ---------------------------------------------------------------------------
__global__ void scatter_pass(const float* __restrict__ src, float* __restrict__ dst,
                             const int*  __restrict__ sn,  const int* __restrict__ en,
                             const float* __restrict__ dfs)
{
    int t = blockIdx.x * blockDim.x + threadIdx.x;
    if (t >= N_EDGES * 12) return;
    int e = t / 12;
    int q = t - e * 12;
    int s = __ldg(sn + e);
    int d = __ldg(en + e);
    float f = __ldg(dfs + e);
    float4 v = __ldg((const float4*)(src + (size_t)s * DIN) + q);
    float* dp = dst + (size_t)d * DIN + q * 4;
    atomicAdd(dp + 0, v.x * f);
    atomicAdd(dp + 1, v.y * f);
    atomicAdd(dp + 2, v.z * f);
    atomicAdd(dp + 3, v.w * f);
}

// ---------------------------------------------------------------------------
// Row-wise scale by degree factor.
// ---------------------------------------------------------------------------
__global__ void scale_pass(float* __restrict__ buf, const float* __restrict__ df)
{
    int i = blockIdx.x * blockDim.x + threadIdx.x;
    if (i >= N_NODES * 12) return;
    int row = i / 12;
    float f = __ldg(df + row);
    float4 v = ((float4*)buf)[i];
    v.x *= f; v.y *= f; v.z *= f; v.w *= f;
    ((float4*)buf)[i] = v;
}

// ---------------------------------------------------------------------------
// Fused MLP: out = relu(x @ W1 + b1) @ W2 + b2
// Block = 256 threads, 64 nodes per block. W1+W2 in smem. Each thread owns an
// 8-node x 4-col register tile (float4 LDS on both operands -> FMA-bound).
// ---------------------------------------------------------------------------
#define MLP_TM 64
#define MLP_THREADS 256
// floats: W1s 6144 | W2s 16384 | b1s 128 | b2s 128 | yt 3072 | ht 8192
#define MLP_SMEM_FLOATS (6144 + 16384 + 128 + 128 + 3072 + 8192)

__global__ void __launch_bounds__(MLP_THREADS, 1)
mlp_kernel(const float* __restrict__ x,
           const float* __restrict__ W1, const float* __restrict__ b1,
           const float* __restrict__ W2, const float* __restrict__ b2,
           float* __restrict__ out)
{
    extern __shared__ float sm[];
    float* W1s = sm;                   // [48][128]
    float* W2s = W1s + 48 * 128;       // [128][128]
    float* b1s = W2s + 128 * 128;      // [128]
    float* b2s = b1s + 128;            // [128]
    float* yt  = b2s + 128;            // [64][48]
    float* ht  = yt + 64 * 48;         // [64][128]

    int tid = threadIdx.x;

    for (int i = tid; i < 48 * 128; i += MLP_THREADS)  W1s[i] = __ldg(W1 + i);
    for (int i = tid; i < 128 * 128; i += MLP_THREADS) W2s[i] = __ldg(W2 + i);
    if (tid < 128) { b1s[tid] = __ldg(b1 + tid); b2s[tid] = __ldg(b2 + tid); }

    int node0 = blockIdx.x * MLP_TM;
    for (int i = tid; i < MLP_TM * 48; i += MLP_THREADS) {
        int r = i / 48;
        int n = node0 + r;
        yt[i] = (n < N_NODES) ? __ldg(x + (size_t)n * 48 + (i - r * 48)) : 0.f;
    }
    __syncthreads();

    int c  = tid & 31;   // column group: cols 4c..4c+3
    int rg = tid >> 5;   // row group: nodes rg*8..rg*8+7

    float acc[8][4];

    // ---- stage 1: h = relu(y @ W1 + b1), K = 48 ----
    {
        float4 bv = ((float4*)b1s)[c];
        #pragma unroll
        for (int m = 0; m < 8; m++) {
            acc[m][0] = bv.x; acc[m][1] = bv.y; acc[m][2] = bv.z; acc[m][3] = bv.w;
        }
        #pragma unroll
        for (int k4 = 0; k4 < 12; k4++) {
            float4 yv[8];
            #pragma unroll
            for (int m = 0; m < 8; m++)
                yv[m] = ((float4*)(yt + (rg * 8 + m) * 48))[k4];
            #pragma unroll
            for (int kk = 0; kk < 4; kk++) {
                float4 wv = ((float4*)(W1s + (k4 * 4 + kk) * 128))[c];
                #pragma unroll
                for (int m = 0; m < 8; m++) {
                    float yk = (kk == 0) ? yv[m].x : (kk == 1) ? yv[m].y
                             : (kk == 2) ? yv[m].z : yv[m].w;
                    acc[m][0] = fmaf(yk, wv.x, acc[m][0]);
                    acc[m][1] = fmaf(yk, wv.y, acc[m][1]);
                    acc[m][2] = fmaf(yk, wv.z, acc[m][2]);
                    acc[m][3] = fmaf(yk, wv.w, acc[m][3]);
                }
            }
        }
        #pragma unroll
        for (int m = 0; m < 8; m++) {
            float4 hv = make_float4(fmaxf(acc[m][0], 0.f), fmaxf(acc[m][1], 0.f),
                                    fmaxf(acc[m][2], 0.f), fmaxf(acc[m][3], 0.f));
            ((float4*)(ht + (rg * 8 + m) * 128))[c] = hv;
        }
    }
    __syncthreads();

    // ---- stage 2: out = h @ W2 + b2, K = 128 ----
    {
        float4 bv = ((float4*)b2s)[c];
        #pragma unroll
        for (int m = 0; m < 8; m++) {
            acc[m][0] = bv.x; acc[m][1] = bv.y; acc[m][2] = bv.z; acc[m][3] = bv.w;
        }
        #pragma unroll
        for (int k4 = 0; k4 < 32; k4++) {
            float4 yv[8];
            #pragma unroll
            for (int m = 0; m < 8; m++)
                yv[m] = ((float4*)(ht + (rg * 8 + m) * 128))[k4];
            #pragma unroll
            for (int kk = 0; kk < 4; kk++) {
                float4 wv = ((float4*)(W2s + (k4 * 4 + kk) * 128))[c];
                #pragma unroll
                for (int m = 0; m < 8; m++) {
                    float yk = (kk == 0) ? yv[m].x : (kk == 1) ? yv[m].y
                             : (kk == 2) ? yv[m].z : yv[m].w;
                    acc[m][0] = fmaf(yk, wv.x, acc[m][0]);
                    acc[m][1] = fmaf(yk, wv.y, acc[m][1]);
                    acc[m][2] = fmaf(yk, wv.z, acc[m][2]);
                    acc[m][3] = fmaf(yk, wv.w, acc[m][3]);
                }
            }
        }
        #pragma unroll
        for (int m = 0; m < 8; m++) {
            int n = node0 + rg * 8 + m;
            if (n < N_NODES) {
                float4 ov = make_float4(acc[m][0], acc[m][1], acc[m][2], acc[m][3]);
                ((float4*)(out + (size_t)n * 128))[c] = ov;
            }
        }
    }
}

// ---------------------------------------------------------------------------
// Echo the passthrough outputs (ints value-cast to float, floats copied).
// ---------------------------------------------------------------------------
__global__ void tail_copy(float* __restrict__ out,
                          const int*  __restrict__ sn, const int* __restrict__ en,
                          const float* __restrict__ dfs, const float* __restrict__ df)
{
    int i = blockIdx.x * blockDim.x + threadIdx.x;
    float* p = out + OUT_ELEMS;
    if (i < N_EDGES) {
        p[i]               = (float)__ldg(sn + i);
        p[N_EDGES + i]     = (float)__ldg(en + i);
        p[2 * N_EDGES + i] = __ldg(dfs + i);
    }
    if (i < N_NODES)
        p[3 * N_EDGES + i] = __ldg(df + i);
}

extern "C" void kernel_launch(void* const* d_in, const int* in_sizes, int n_in,
                              void* d_out, int out_size)
{
    const float* y   = (const float*)d_in[0];
    const int*   sn  = (const int*)  d_in[1];
    const int*   en  = (const int*)  d_in[2];
    const float* dfs = (const float*)d_in[3];
    const float* df  = (const float*)d_in[4];
    const float* W1  = (const float*)d_in[5];
    const float* b1  = (const float*)d_in[6];
    const float* W2  = (const float*)d_in[7];
    const float* b2  = (const float*)d_in[8];
    float* out = (float*)d_out;

    float *bufA, *bufB;
    cudaGetSymbolAddress((void**)&bufA, g_bufA);
    cudaGetSymbolAddress((void**)&bufB, g_bufB);

    cudaFuncSetAttribute(mlp_kernel, cudaFuncAttributeMaxDynamicSharedMemorySize,
                         MLP_SMEM_FLOATS * (int)sizeof(float));

    const int ZB = (N_NODES * DIN / 4 + 255) / 256;
    const int SB = (N_EDGES * 12 + 255) / 256;
    const int CB = (N_NODES * 12 + 255) / 256;

    zero_bufs<<<ZB, 256>>>();

    // pass 1: y -> bufA
    scatter_pass<<<SB, 256>>>(y, bufA, sn, en, dfs);
    scale_pass<<<CB, 256>>>(bufA, df);

    // pass 2: bufA -> bufB
    scatter_pass<<<SB, 256>>>(bufA, bufB, sn, en, dfs);
    scale_pass<<<CB, 256>>>(bufB, df);

    // fused MLP -> out
    mlp_kernel<<<(N_NODES + MLP_TM - 1) / MLP_TM, MLP_THREADS,
                 MLP_SMEM_FLOATS * sizeof(float)>>>(bufB, W1, b1, W2, b2, out);

    // passthrough echoes, only if the output buffer holds the full tuple
    if (out_size >= FULL_OUT) {
        tail_copy<<<(N_EDGES + 255) / 256, 256>>>(out, sn, en, dfs, df);
    }
}

// round 2
// speedup vs baseline: 1.5589x; 1.5589x over previous
#include <cuda_runtime.h>

#define N_NODES 100000
#define N_EDGES 1600000
#define DIN 48
#define DOUT 128
#define OUT_ELEMS (N_NODES * DOUT)                     // 12,800,000
#define FULL_OUT  (OUT_ELEMS + 3 * N_EDGES + N_NODES)  // 17,700,000

// Scratch node-feature buffers (19.2 MB each) — L2-resident working set.
__device__ float g_bufA[(size_t)N_NODES * DIN];
__device__ float g_bufB[(size_t)N_NODES * DIN];

// ---------------------------------------------------------------------------
// Vectorized global float4 reduction (sm_90+).
// ---------------------------------------------------------------------------
__device__ __forceinline__ void red_add_v4(float* addr, float x, float y, float z, float w)
{
    asm volatile("red.global.add.v4.f32 [%0], {%1, %2, %3, %4};"
                 :: "l"(addr), "f"(x), "f"(y), "f"(z), "f"(w) : "memory");
}

// ---------------------------------------------------------------------------
// Zero both scratch buffers (float4 vectorized).
// ---------------------------------------------------------------------------
__global__ void zero_bufs()
{
    int i = blockIdx.x * blockDim.x + threadIdx.x;
    if (i < N_NODES * DIN / 4) {
        ((float4*)g_bufA)[i] = make_float4(0.f, 0.f, 0.f, 0.f);
        ((float4*)g_bufB)[i] = make_float4(0.f, 0.f, 0.f, 0.f);
    }
}

// ---------------------------------------------------------------------------
// Message-passing scatter: dst[end[e]] += src[start[e]] * dfs[e] (* df[start[e]])
// 12 threads per edge, one float4 chunk each. USE_DF folds the destination-side
// degree scaling of the PREVIOUS pass into this pass's edge factor.
// ---------------------------------------------------------------------------
template <bool USE_DF>
__global__ void scatter_pass(const float* __restrict__ src, float* __restrict__ dst,
                             const int*  __restrict__ sn,  const int* __restrict__ en,
                             const float* __restrict__ dfs, const float* __restrict__ df)
{
    int t = blockIdx.x * blockDim.x + threadIdx.x;
    if (t >= N_EDGES * 12) return;
    int e = t / 12;
    int q = t - e * 12;
    int s = __ldg(sn + e);
    int d = __ldg(en + e);
    float f = __ldg(dfs + e);
    if (USE_DF) f *= __ldg(df + s);
    float4 v = __ldg((const float4*)(src + (size_t)s * DIN) + q);
    float* dp = dst + (size_t)d * DIN + q * 4;
    red_add_v4(dp, v.x * f, v.y * f, v.z * f, v.w * f);
}

// ---------------------------------------------------------------------------
// Fused MLP: out = relu((x*df) @ W1 + b1) @ W2 + b2
// Block = 256 threads, 64 nodes per block. W1+W2 in smem. Each thread owns an
// 8-node x 4-col register tile (float4 LDS on both operands -> FMA-bound).
// The final degree scaling of pass 2 is folded into the smem load of x.
// ---------------------------------------------------------------------------
#define MLP_TM 64
#define MLP_THREADS 256
#define MLP_SMEM_FLOATS (6144 + 16384 + 128 + 128 + 3072 + 8192)

__global__ void __launch_bounds__(MLP_THREADS, 1)
mlp_kernel(const float* __restrict__ x, const float* __restrict__ df,
           const float* __restrict__ W1, const float* __restrict__ b1,
           const float* __restrict__ W2, const float* __restrict__ b2,
           float* __restrict__ out)
{
    extern __shared__ float sm[];
    float* W1s = sm;                   // [48][128]
    float* W2s = W1s + 48 * 128;       // [128][128]
    float* b1s = W2s + 128 * 128;      // [128]
    float* b2s = b1s + 128;            // [128]
    float* yt  = b2s + 128;            // [64][48]
    float* ht  = yt + 64 * 48;         // [64][128]

    int tid = threadIdx.x;

    for (int i = tid; i < 48 * 128; i += MLP_THREADS)  W1s[i] = __ldg(W1 + i);
    for (int i = tid; i < 128 * 128; i += MLP_THREADS) W2s[i] = __ldg(W2 + i);
    if (tid < 128) { b1s[tid] = __ldg(b1 + tid); b2s[tid] = __ldg(b2 + tid); }

    int node0 = blockIdx.x * MLP_TM;
    for (int i = tid; i < MLP_TM * 48; i += MLP_THREADS) {
        int r = i / 48;
        int n = node0 + r;
        yt[i] = (n < N_NODES) ? __ldg(x + (size_t)n * 48 + (i - r * 48)) * __ldg(df + n)
                              : 0.f;
    }
    __syncthreads();

    int c  = tid & 31;   // column group: cols 4c..4c+3
    int rg = tid >> 5;   // row group: nodes rg*8..rg*8+7

    float acc[8][4];

    // ---- stage 1: h = relu(y @ W1 + b1), K = 48 ----
    {
        float4 bv = ((float4*)b1s)[c];
        #pragma unroll
        for (int m = 0; m < 8; m++) {
            acc[m][0] = bv.x; acc[m][1] = bv.y; acc[m][2] = bv.z; acc[m][3] = bv.w;
        }
        #pragma unroll
        for (int k4 = 0; k4 < 12; k4++) {
            float4 yv[8];
            #pragma unroll
            for (int m = 0; m < 8; m++)
                yv[m] = ((float4*)(yt + (rg * 8 + m) * 48))[k4];
            #pragma unroll
            for (int kk = 0; kk < 4; kk++) {
                float4 wv = ((float4*)(W1s + (k4 * 4 + kk) * 128))[c];
                #pragma unroll
                for (int m = 0; m < 8; m++) {
                    float yk = (kk == 0) ? yv[m].x : (kk == 1) ? yv[m].y
                             : (kk == 2) ? yv[m].z : yv[m].w;
                    acc[m][0] = fmaf(yk, wv.x, acc[m][0]);
                    acc[m][1] = fmaf(yk, wv.y, acc[m][1]);
                    acc[m][2] = fmaf(yk, wv.z, acc[m][2]);
                    acc[m][3] = fmaf(yk, wv.w, acc[m][3]);
                }
            }
        }
        #pragma unroll
        for (int m = 0; m < 8; m++) {
            float4 hv = make_float4(fmaxf(acc[m][0], 0.f), fmaxf(acc[m][1], 0.f),
                                    fmaxf(acc[m][2], 0.f), fmaxf(acc[m][3], 0.f));
            ((float4*)(ht + (rg * 8 + m) * 128))[c] = hv;
        }
    }
    __syncthreads();

    // ---- stage 2: out = h @ W2 + b2, K = 128 ----
    {
        float4 bv = ((float4*)b2s)[c];
        #pragma unroll
        for (int m = 0; m < 8; m++) {
            acc[m][0] = bv.x; acc[m][1] = bv.y; acc[m][2] = bv.z; acc[m][3] = bv.w;
        }
        #pragma unroll
        for (int k4 = 0; k4 < 32; k4++) {
            float4 yv[8];
            #pragma unroll
            for (int m = 0; m < 8; m++)
                yv[m] = ((float4*)(ht + (rg * 8 + m) * 128))[k4];
            #pragma unroll
            for (int kk = 0; kk < 4; kk++) {
                float4 wv = ((float4*)(W2s + (k4 * 4 + kk) * 128))[c];
                #pragma unroll
                for (int m = 0; m < 8; m++) {
                    float yk = (kk == 0) ? yv[m].x : (kk == 1) ? yv[m].y
                             : (kk == 2) ? yv[m].z : yv[m].w;
                    acc[m][0] = fmaf(yk, wv.x, acc[m][0]);
                    acc[m][1] = fmaf(yk, wv.y, acc[m][1]);
                    acc[m][2] = fmaf(yk, wv.z, acc[m][2]);
                    acc[m][3] = fmaf(yk, wv.w, acc[m][3]);
                }
            }
        }
        #pragma unroll
        for (int m = 0; m < 8; m++) {
            int n = node0 + rg * 8 + m;
            if (n < N_NODES) {
                float4 ov = make_float4(acc[m][0], acc[m][1], acc[m][2], acc[m][3]);
                ((float4*)(out + (size_t)n * 128))[c] = ov;
            }
        }
    }
}

// ---------------------------------------------------------------------------
// Echo the passthrough outputs (ints value-cast to float, floats copied).
// ---------------------------------------------------------------------------
__global__ void tail_copy(float* __restrict__ out,
                          const int*  __restrict__ sn, const int* __restrict__ en,
                          const float* __restrict__ dfs, const float* __restrict__ df)
{
    int i = blockIdx.x * blockDim.x + threadIdx.x;
    float* p = out + OUT_ELEMS;
    if (i < N_EDGES) {
        p[i]               = (float)__ldg(sn + i);
        p[N_EDGES + i]     = (float)__ldg(en + i);
        p[2 * N_EDGES + i] = __ldg(dfs + i);
    }
    if (i < N_NODES)
        p[3 * N_EDGES + i] = __ldg(df + i);
}

extern "C" void kernel_launch(void* const* d_in, const int* in_sizes, int n_in,
                              void* d_out, int out_size)
{
    const float* y   = (const float*)d_in[0];
    const int*   sn  = (const int*)  d_in[1];
    const int*   en  = (const int*)  d_in[2];
    const float* dfs = (const float*)d_in[3];
    const float* df  = (const float*)d_in[4];
    const float* W1  = (const float*)d_in[5];
    const float* b1  = (const float*)d_in[6];
    const float* W2  = (const float*)d_in[7];
    const float* b2  = (const float*)d_in[8];
    float* out = (float*)d_out;

    float *bufA, *bufB;
    cudaGetSymbolAddress((void**)&bufA, g_bufA);
    cudaGetSymbolAddress((void**)&bufB, g_bufB);

    cudaFuncSetAttribute(mlp_kernel, cudaFuncAttributeMaxDynamicSharedMemorySize,
                         MLP_SMEM_FLOATS * (int)sizeof(float));

    const int ZB = (N_NODES * DIN / 4 + 255) / 256;
    const int SB = (N_EDGES * 12 + 255) / 256;

    zero_bufs<<<ZB, 256>>>();

    // pass 1: bufA = segsum(y[s] * dfs[e])             (unscaled)
    scatter_pass<false><<<SB, 256>>>(y, bufA, sn, en, dfs, df);

    // pass 2: bufB = segsum(bufA[s] * df[s] * dfs[e])  (pass-1 df folded in)
    scatter_pass<true><<<SB, 256>>>(bufA, bufB, sn, en, dfs, df);

    // fused MLP -> out (pass-2 df folded into the x load)
    mlp_kernel<<<(N_NODES + MLP_TM - 1) / MLP_TM, MLP_THREADS,
                 MLP_SMEM_FLOATS * sizeof(float)>>>(bufB, df, W1, b1, W2, b2, out);

    // passthrough echoes, only if the output buffer holds the full tuple
    if (out_size >= FULL_OUT) {
        tail_copy<<<(N_EDGES + 255) / 256, 256>>>(out, sn, en, dfs, df);
    }
}

// round 3
// speedup vs baseline: 1.6791x; 1.0771x over previous
#include <cuda_runtime.h>

#define N_NODES 100000
#define N_EDGES 1600000
#define DIN 48
#define DOUT 128
#define OUT_ELEMS (N_NODES * DOUT)                     // 12,800,000
#define FULL_OUT  (OUT_ELEMS + 3 * N_EDGES + N_NODES)  // 17,700,000

// Scratch node-feature buffers (19.2 MB each) — L2-resident working set.
__device__ float g_bufA[(size_t)N_NODES * DIN];
__device__ float g_bufB[(size_t)N_NODES * DIN];

// ---------------------------------------------------------------------------
// Vectorized global float4 reduction (sm_90+).
// ---------------------------------------------------------------------------
__device__ __forceinline__ void red_add_v4(float* addr, float x, float y, float z, float w)
{
    asm volatile("red.global.add.v4.f32 [%0], {%1, %2, %3, %4};"
                 :: "l"(addr), "f"(x), "f"(y), "f"(z), "f"(w) : "memory");
}

// ---------------------------------------------------------------------------
// Zero both scratch buffers (float4 vectorized).
// ---------------------------------------------------------------------------
__global__ void zero_bufs()
{
    int i = blockIdx.x * blockDim.x + threadIdx.x;
    if (i < N_NODES * DIN / 4) {
        ((float4*)g_bufA)[i] = make_float4(0.f, 0.f, 0.f, 0.f);
        ((float4*)g_bufB)[i] = make_float4(0.f, 0.f, 0.f, 0.f);
    }
}

// ---------------------------------------------------------------------------
// Message-passing scatter: dst[end[e]] += src[start[e]] * dfs[e] (* df[start[e]])
// 12 threads per edge, one float4 chunk each. USE_DF folds the destination-side
// degree scaling of the PREVIOUS pass into this pass's edge factor.
// ---------------------------------------------------------------------------
template <bool USE_DF>
__global__ void scatter_pass(const float* __restrict__ src, float* __restrict__ dst,
                             const int*  __restrict__ sn,  const int* __restrict__ en,
                             const float* __restrict__ dfs, const float* __restrict__ df)
{
    int t = blockIdx.x * blockDim.x + threadIdx.x;
    if (t >= N_EDGES * 12) return;
    int e = t / 12;
    int q = t - e * 12;
    int s = __ldg(sn + e);
    int d = __ldg(en + e);
    float f = __ldg(dfs + e);
    if (USE_DF) f *= __ldg(df + s);
    float4 v = __ldg((const float4*)(src + (size_t)s * DIN) + q);
    float* dp = dst + (size_t)d * DIN + q * 4;
    red_add_v4(dp, v.x * f, v.y * f, v.z * f, v.w * f);
}

// ---------------------------------------------------------------------------
// Fused MLP: out = relu((x*df) @ W1 + b1) @ W2 + b2
// Block = 512 threads, 128 nodes per block (16 warps/SM -> 4 per SMSP, enough
// to hide LDS latency). W1+W2 staged once per block in smem. Each thread owns
// an 8-node x 4-col register tile (float4 LDS on both operands).
// ---------------------------------------------------------------------------
#define MLP_TM 128
#define MLP_THREADS 512
// floats: W1s 6144 | W2s 16384 | b1s 128 | b2s 128 | yt 6144 | ht 16384
#define MLP_SMEM_FLOATS (6144 + 16384 + 128 + 128 + 6144 + 16384)

__global__ void __launch_bounds__(MLP_THREADS, 1)
mlp_kernel(const float* __restrict__ x, const float* __restrict__ df,
           const float* __restrict__ W1, const float* __restrict__ b1,
           const float* __restrict__ W2, const float* __restrict__ b2,
           float* __restrict__ out)
{
    extern __shared__ float sm[];
    float* W1s = sm;                   // [48][128]
    float* W2s = W1s + 48 * 128;       // [128][128]
    float* b1s = W2s + 128 * 128;      // [128]
    float* b2s = b1s + 128;            // [128]
    float* yt  = b2s + 128;            // [128][48]
    float* ht  = yt + MLP_TM * 48;     // [128][128]

    int tid = threadIdx.x;

    for (int i = tid; i < 48 * 128; i += MLP_THREADS)  W1s[i] = __ldg(W1 + i);
    for (int i = tid; i < 128 * 128; i += MLP_THREADS) W2s[i] = __ldg(W2 + i);
    if (tid < 128) { b1s[tid] = __ldg(b1 + tid); b2s[tid] = __ldg(b2 + tid); }

    int node0 = blockIdx.x * MLP_TM;
    for (int i = tid; i < MLP_TM * 48; i += MLP_THREADS) {
        int r = i / 48;
        int n = node0 + r;
        yt[i] = (n < N_NODES) ? __ldg(x + (size_t)n * 48 + (i - r * 48)) * __ldg(df + n)
                              : 0.f;
    }
    __syncthreads();

    int c  = tid & 31;   // column group: cols 4c..4c+3
    int rg = tid >> 5;   // row group: nodes rg*8..rg*8+7 (0..15)

    float acc[8][4];

    // ---- stage 1: h = relu(y @ W1 + b1), K = 48 ----
    {
        float4 bv = ((float4*)b1s)[c];
        #pragma unroll
        for (int m = 0; m < 8; m++) {
            acc[m][0] = bv.x; acc[m][1] = bv.y; acc[m][2] = bv.z; acc[m][3] = bv.w;
        }
        #pragma unroll
        for (int k4 = 0; k4 < 12; k4++) {
            float4 yv[8];
            #pragma unroll
            for (int m = 0; m < 8; m++)
                yv[m] = ((float4*)(yt + (rg * 8 + m) * 48))[k4];
            #pragma unroll
            for (int kk = 0; kk < 4; kk++) {
                float4 wv = ((float4*)(W1s + (k4 * 4 + kk) * 128))[c];
                #pragma unroll
                for (int m = 0; m < 8; m++) {
                    float yk = (kk == 0) ? yv[m].x : (kk == 1) ? yv[m].y
                             : (kk == 2) ? yv[m].z : yv[m].w;
                    acc[m][0] = fmaf(yk, wv.x, acc[m][0]);
                    acc[m][1] = fmaf(yk, wv.y, acc[m][1]);
                    acc[m][2] = fmaf(yk, wv.z, acc[m][2]);
                    acc[m][3] = fmaf(yk, wv.w, acc[m][3]);
                }
            }
        }
        #pragma unroll
        for (int m = 0; m < 8; m++) {
            float4 hv = make_float4(fmaxf(acc[m][0], 0.f), fmaxf(acc[m][1], 0.f),
                                    fmaxf(acc[m][2], 0.f), fmaxf(acc[m][3], 0.f));
            ((float4*)(ht + (rg * 8 + m) * 128))[c] = hv;
        }
    }
    __syncthreads();

    // ---- stage 2: out = h @ W2 + b2, K = 128 ----
    {
        float4 bv = ((float4*)b2s)[c];
        #pragma unroll
        for (int m = 0; m < 8; m++) {
            acc[m][0] = bv.x; acc[m][1] = bv.y; acc[m][2] = bv.z; acc[m][3] = bv.w;
        }
        #pragma unroll
        for (int k4 = 0; k4 < 32; k4++) {
            float4 yv[8];
            #pragma unroll
            for (int m = 0; m < 8; m++)
                yv[m] = ((float4*)(ht + (rg * 8 + m) * 128))[k4];
            #pragma unroll
            for (int kk = 0; kk < 4; kk++) {
                float4 wv = ((float4*)(W2s + (k4 * 4 + kk) * 128))[c];
                #pragma unroll
                for (int m = 0; m < 8; m++) {
                    float yk = (kk == 0) ? yv[m].x : (kk == 1) ? yv[m].y
                             : (kk == 2) ? yv[m].z : yv[m].w;
                    acc[m][0] = fmaf(yk, wv.x, acc[m][0]);
                    acc[m][1] = fmaf(yk, wv.y, acc[m][1]);
                    acc[m][2] = fmaf(yk, wv.z, acc[m][2]);
                    acc[m][3] = fmaf(yk, wv.w, acc[m][3]);
                }
            }
        }
        #pragma unroll
        for (int m = 0; m < 8; m++) {
            int n = node0 + rg * 8 + m;
            if (n < N_NODES) {
                float4 ov = make_float4(acc[m][0], acc[m][1], acc[m][2], acc[m][3]);
                ((float4*)(out + (size_t)n * 128))[c] = ov;
            }
        }
    }
}

// ---------------------------------------------------------------------------
// Echo the passthrough outputs (ints value-cast to float, floats copied).
// ---------------------------------------------------------------------------
__global__ void tail_copy(float* __restrict__ out,
                          const int*  __restrict__ sn, const int* __restrict__ en,
                          const float* __restrict__ dfs, const float* __restrict__ df)
{
    int i = blockIdx.x * blockDim.x + threadIdx.x;
    float* p = out + OUT_ELEMS;
    if (i < N_EDGES) {
        p[i]               = (float)__ldg(sn + i);
        p[N_EDGES + i]     = (float)__ldg(en + i);
        p[2 * N_EDGES + i] = __ldg(dfs + i);
    }
    if (i < N_NODES)
        p[3 * N_EDGES + i] = __ldg(df + i);
}

extern "C" void kernel_launch(void* const* d_in, const int* in_sizes, int n_in,
                              void* d_out, int out_size)
{
    const float* y   = (const float*)d_in[0];
    const int*   sn  = (const int*)  d_in[1];
    const int*   en  = (const int*)  d_in[2];
    const float* dfs = (const float*)d_in[3];
    const float* df  = (const float*)d_in[4];
    const float* W1  = (const float*)d_in[5];
    const float* b1  = (const float*)d_in[6];
    const float* W2  = (const float*)d_in[7];
    const float* b2  = (const float*)d_in[8];
    float* out = (float*)d_out;

    float *bufA, *bufB;
    cudaGetSymbolAddress((void**)&bufA, g_bufA);
    cudaGetSymbolAddress((void**)&bufB, g_bufB);

    cudaFuncSetAttribute(mlp_kernel, cudaFuncAttributeMaxDynamicSharedMemorySize,
                         MLP_SMEM_FLOATS * (int)sizeof(float));

    const int ZB = (N_NODES * DIN / 4 + 255) / 256;
    const int SB = (N_EDGES * 12 + 255) / 256;

    zero_bufs<<<ZB, 256>>>();

    // pass 1: bufA = segsum(y[s] * dfs[e])             (unscaled)
    scatter_pass<false><<<SB, 256>>>(y, bufA, sn, en, dfs, df);

    // pass 2: bufB = segsum(bufA[s] * df[s] * dfs[e])  (pass-1 df folded in)
    scatter_pass<true><<<SB, 256>>>(bufA, bufB, sn, en, dfs, df);

    // fused MLP -> out (pass-2 df folded into the x load)
    mlp_kernel<<<(N_NODES + MLP_TM - 1) / MLP_TM, MLP_THREADS,
                 MLP_SMEM_FLOATS * sizeof(float)>>>(bufB, df, W1, b1, W2, b2, out);

    // passthrough echoes, only if the output buffer holds the full tuple
    if (out_size >= FULL_OUT) {
        tail_copy<<<(N_EDGES + 255) / 256, 256>>>(out, sn, en, dfs, df);
    }
}